// round 1
// baseline (speedup 1.0000x reference)
#include <cuda_runtime.h>

#define NN 50000
#define EE 800000
#define F  64
#define NG 64

// ---------------- scratch (device globals; no allocation allowed) ----------
__device__ float g_dinv_in [NN];
__device__ float g_dinv_out[NN];
__device__ float g_pin   [NN * F];
__device__ float g_pout  [NN * F];
__device__ float g_accin [NN * F];
__device__ float g_accout[NN * F];
__device__ float g_h     [NN * F];
__device__ float g_pool  [NG * F];
__device__ float g_cnt   [NG];

// ---------------- init: degrees start at 1 (self-loop), pool zeroed --------
__global__ void k_init(int n) {
    int t = blockIdx.x * blockDim.x + threadIdx.x;
    if (t < n) { g_dinv_in[t] = 1.0f; g_dinv_out[t] = 1.0f; }
    if (t < NG * F) g_pool[t] = 0.0f;
    if (t < NG) g_cnt[t] = 0.0f;
}

// ---------------- degree accumulation over edges ----------------------------
__global__ void k_degree(const int* __restrict__ src, const int* __restrict__ dst, int e) {
    int t = blockIdx.x * blockDim.x + threadIdx.x;
    if (t < e) {
        atomicAdd(&g_dinv_in[dst[t]], 1.0f);
        atomicAdd(&g_dinv_out[src[t]], 1.0f);
    }
}

__global__ void k_dinv(int n) {
    int t = blockIdx.x * blockDim.x + threadIdx.x;
    if (t < n) {
        g_dinv_in[t]  = rsqrtf(g_dinv_in[t]);
        g_dinv_out[t] = rsqrtf(g_dinv_out[t]);
    }
}

// ---------------- fused dual GEMM + dinv pre-scale + self-loop init --------
// p_in  = (x @ W_in ) * dinv_in[row]   ; acc_in  initialized to p_in
// p_out = (x @ W_out) * dinv_out[row]  ; acc_out initialized to p_out
// xin == nullptr means "read g_h" (layers 2,3).
__global__ __launch_bounds__(512) void k_gemm(const float* __restrict__ xin,
                                              const float* __restrict__ Win,
                                              const float* __restrict__ Wout,
                                              int n) {
    __shared__ float xs[32 * 64];
    __shared__ float wi[64 * 64];
    __shared__ float wo[64 * 64];
    const float* x = xin ? xin : g_h;

    int tid = threadIdx.x;                 // 512 threads
    // load weight matrices (row-major [k][f]) into shared, float4
    {
        float4* wi4 = (float4*)wi; const float4* Wi4 = (const float4*)Win;
        float4* wo4 = (float4*)wo; const float4* Wo4 = (const float4*)Wout;
        #pragma unroll
        for (int i = tid; i < 1024; i += 512) { wi4[i] = Wi4[i]; wo4[i] = Wo4[i]; }
    }
    int base = blockIdx.x * 32;
    // load 32 rows of x into shared
    {
        const float4* x4 = (const float4*)x;
        int i = tid;                       // 512 float4s exactly
        int r = i >> 4, c = i & 15;
        int row = base + r;
        ((float4*)xs)[i] = (row < n) ? x4[row * 16 + c] : make_float4(0.f, 0.f, 0.f, 0.f);
    }
    __syncthreads();

    int lr = tid >> 4;                     // local row 0..31
    int fq = tid & 15;                     // float4 column group 0..15
    int row = base + lr;
    if (row >= n) return;

    float4 ai = make_float4(0.f, 0.f, 0.f, 0.f);
    float4 ao = make_float4(0.f, 0.f, 0.f, 0.f);
    const float4* wi4 = (const float4*)wi;
    const float4* wo4 = (const float4*)wo;
    #pragma unroll
    for (int k = 0; k < 64; k++) {
        float xk = xs[lr * 64 + k];
        float4 a = wi4[k * 16 + fq];
        float4 b = wo4[k * 16 + fq];
        ai.x += xk * a.x; ai.y += xk * a.y; ai.z += xk * a.z; ai.w += xk * a.w;
        ao.x += xk * b.x; ao.y += xk * b.y; ao.z += xk * b.z; ao.w += xk * b.w;
    }
    float di = g_dinv_in[row], dq = g_dinv_out[row];
    float4 pi = make_float4(ai.x * di, ai.y * di, ai.z * di, ai.w * di);
    float4 po = make_float4(ao.x * dq, ao.y * dq, ao.z * dq, ao.w * dq);
    int off = row * 16 + fq;
    ((float4*)g_pin )[off] = pi;  ((float4*)g_accin )[off] = pi;   // self-loop
    ((float4*)g_pout)[off] = po;  ((float4*)g_accout)[off] = po;   // self-loop
}

// ---------------- edge scatter: both directions ------------------------------
// acc_in[dst] += p_in[src] ; acc_out[src] += p_out[dst]
__global__ void k_scatter(const int* __restrict__ src, const int* __restrict__ dst, int e) {
    int t = blockIdx.x * blockDim.x + threadIdx.x;
    int eid = t >> 4;
    if (eid >= e) return;
    int f4 = t & 15;
    int s = src[eid], d = dst[eid];

    float4 vi = ((const float4*)g_pin)[s * 16 + f4];
    float* ad = g_accin + d * 64 + f4 * 4;
    atomicAdd(ad + 0, vi.x); atomicAdd(ad + 1, vi.y);
    atomicAdd(ad + 2, vi.z); atomicAdd(ad + 3, vi.w);

    float4 vo = ((const float4*)g_pout)[d * 16 + f4];
    float* as = g_accout + s * 64 + f4 * 4;
    atomicAdd(as + 0, vo.x); atomicAdd(as + 1, vo.y);
    atomicAdd(as + 2, vo.z); atomicAdd(as + 3, vo.w);
}

// ---------------- combine: post-scale, bias, alpha-mix, relu ---------------
__global__ void k_combine(const float* __restrict__ bin, const float* __restrict__ bout,
                          int n, int doRelu) {
    int t = blockIdx.x * blockDim.x + threadIdx.x;
    if (t >= n * 16) return;
    int row = t >> 4, fq = t & 15;
    float di = g_dinv_in[row], dq = g_dinv_out[row];
    float4 ai = ((const float4*)g_accin)[t];
    float4 ao = ((const float4*)g_accout)[t];
    float4 bi = ((const float4*)bin)[fq];
    float4 bo = ((const float4*)bout)[fq];
    float4 r;
    r.x = 0.5f * (ao.x * dq + bo.x) + 0.5f * (ai.x * di + bi.x);
    r.y = 0.5f * (ao.y * dq + bo.y) + 0.5f * (ai.y * di + bi.y);
    r.z = 0.5f * (ao.z * dq + bo.z) + 0.5f * (ai.z * di + bi.z);
    r.w = 0.5f * (ao.w * dq + bo.w) + 0.5f * (ai.w * di + bi.w);
    if (doRelu) {
        r.x = fmaxf(r.x, 0.f); r.y = fmaxf(r.y, 0.f);
        r.z = fmaxf(r.z, 0.f); r.w = fmaxf(r.w, 0.f);
    }
    ((float4*)g_h)[t] = r;
}

// ---------------- pooling: shared per-graph accumulators --------------------
__global__ void k_pool(const int* __restrict__ batch, int n) {
    __shared__ float sm[NG * F];
    __shared__ float smc[NG];
    int tid = threadIdx.x;                 // 256
    for (int i = tid; i < NG * F; i += 256) sm[i] = 0.f;
    if (tid < NG) smc[tid] = 0.f;
    __syncthreads();

    int per = (n + gridDim.x - 1) / gridDim.x;
    int b0 = blockIdx.x * per;
    int b1 = min(n, b0 + per);
    for (int i = b0 * 64 + tid; i < b1 * 64; i += 256) {
        int node = i >> 6, f = i & 63;
        atomicAdd(&sm[batch[node] * 64 + f], g_h[i]);
    }
    for (int node = b0 + tid; node < b1; node += 256)
        atomicAdd(&smc[batch[node]], 1.0f);
    __syncthreads();

    for (int i = tid; i < NG * F; i += 256)
        if (sm[i] != 0.f) atomicAdd(&g_pool[i], sm[i]);
    if (tid < NG && smc[tid] != 0.f) atomicAdd(&g_cnt[tid], smc[tid]);
}

// ---------------- head: mean-pool divide, LayerNorm, MLP -------------------
__global__ void k_head(const float* __restrict__ lnw, const float* __restrict__ lnb,
                       const float* __restrict__ P1w, const float* __restrict__ P1b,
                       const float* __restrict__ P2w, const float* __restrict__ P2b,
                       float* __restrict__ out) {
    __shared__ float z [NG * F];     // 16 KB
    __shared__ float h1[NG * 128];   // 32 KB
    int tid = threadIdx.x;           // 128

    if (tid < NG) {
        int g = tid;
        float c = fmaxf(g_cnt[g], 1.0f);
        float inv = 1.0f / c;
        float mu = 0.f;
        for (int f = 0; f < 64; f++) mu += g_pool[g * 64 + f];
        mu *= inv * (1.0f / 64.0f);
        float var = 0.f;
        for (int f = 0; f < 64; f++) {
            float d = g_pool[g * 64 + f] * inv - mu;
            var += d * d;
        }
        var *= (1.0f / 64.0f);
        float rs = rsqrtf(var + 1e-5f);
        for (int f = 0; f < 64; f++)
            z[g * 64 + f] = (g_pool[g * 64 + f] * inv - mu) * rs * lnw[f] + lnb[f];
    }
    __syncthreads();

    for (int idx = tid; idx < NG * 128; idx += 128) {
        int g = idx >> 7, j = idx & 127;
        float s = P1b[j];
        for (int k = 0; k < 64; k++) s += z[g * 64 + k] * P1w[k * 128 + j];
        h1[idx] = fmaxf(s, 0.f);
    }
    __syncthreads();

    {
        int g = tid >> 1, o = tid & 1;
        float s = P2b[o];
        for (int j = 0; j < 128; j++) s += h1[g * 128 + j] * P2w[j * 2 + o];
        out[g * 2 + o] = s;
    }
}

// ---------------- launch -----------------------------------------------------
extern "C" void kernel_launch(void* const* d_in, const int* in_sizes, int n_in,
                              void* d_out, int out_size) {
    const float* x     = (const float*)d_in[0];
    const int*   src   = (const int*)  d_in[1];
    const int*   dst   = (const int*)  d_in[2];
    const int*   batch = (const int*)  d_in[3];
    const float* W1_in = (const float*)d_in[4];
    const float* b1_in = (const float*)d_in[5];
    const float* W1_out= (const float*)d_in[6];
    const float* b1_out= (const float*)d_in[7];
    const float* W2_in = (const float*)d_in[8];
    const float* b2_in = (const float*)d_in[9];
    const float* W2_out= (const float*)d_in[10];
    const float* b2_out= (const float*)d_in[11];
    const float* W3_in = (const float*)d_in[12];
    const float* b3_in = (const float*)d_in[13];
    const float* W3_out= (const float*)d_in[14];
    const float* b3_out= (const float*)d_in[15];
    const float* ln_w  = (const float*)d_in[16];
    const float* ln_b  = (const float*)d_in[17];
    const float* P1_w  = (const float*)d_in[18];
    const float* P1_b  = (const float*)d_in[19];
    const float* P2_w  = (const float*)d_in[20];
    const float* P2_b  = (const float*)d_in[21];
    float* out = (float*)d_out;

    int n = in_sizes[0] / 64;   // 50000
    int e = in_sizes[1];        // 800000

    int ib = (n + 255) / 256;
    k_init<<<ib, 256>>>(n);
    k_degree<<<(e + 255) / 256, 256>>>(src, dst, e);
    k_dinv<<<ib, 256>>>(n);

    int gemmBlocks = (n + 31) / 32;
    int scatBlocks = (e * 16 + 255) / 256;
    int combBlocks = (n * 16 + 255) / 256;

    // layer 1
    k_gemm<<<gemmBlocks, 512>>>(x, W1_in, W1_out, n);
    k_scatter<<<scatBlocks, 256>>>(src, dst, e);
    k_combine<<<combBlocks, 256>>>(b1_in, b1_out, n, 1);
    // layer 2
    k_gemm<<<gemmBlocks, 512>>>(nullptr, W2_in, W2_out, n);
    k_scatter<<<scatBlocks, 256>>>(src, dst, e);
    k_combine<<<combBlocks, 256>>>(b2_in, b2_out, n, 1);
    // layer 3
    k_gemm<<<gemmBlocks, 512>>>(nullptr, W3_in, W3_out, n);
    k_scatter<<<scatBlocks, 256>>>(src, dst, e);
    k_combine<<<combBlocks, 256>>>(b3_in, b3_out, n, 0);

    k_pool<<<128, 256>>>(batch, n);
    k_head<<<1, 128>>>(ln_w, ln_b, P1_w, P1_b, P2_w, P2_b, out);
}

// round 2
// speedup vs baseline: 2.0311x; 2.0311x over previous
#include <cuda_runtime.h>

#define NN 50000
#define EE 800000
#define F  64
#define NG 64

// ---------------- scratch (device globals) ----------------------------------
__device__ float g_dinv_in [NN];
__device__ float g_dinv_out[NN];
__device__ float g_pin   [NN * F];
__device__ float g_pout  [NN * F];
__device__ float g_h     [NN * F];
__device__ float g_pool  [NG * F];
__device__ float g_cnt   [NG];

__device__ int g_cntin [NN];
__device__ int g_cntout[NN];
__device__ int g_offin [NN + 1];
__device__ int g_offout[NN + 1];
__device__ int g_curin [NN];
__device__ int g_curout[NN];
__device__ int g_csrin [EE];
__device__ int g_csrout[EE];

// ---------------- init -------------------------------------------------------
__global__ void k_init(int n) {
    int t = blockIdx.x * blockDim.x + threadIdx.x;
    if (t < n) { g_cntin[t] = 0; g_cntout[t] = 0; }
    if (t < NG * F) g_pool[t] = 0.0f;
    if (t < NG) g_cnt[t] = 0.0f;
}

// ---------------- degree / CSR histogram ------------------------------------
__global__ void k_count(const int* __restrict__ src, const int* __restrict__ dst, int e) {
    int t = blockIdx.x * blockDim.x + threadIdx.x;
    if (t < e) {
        atomicAdd(&g_cntin [dst[t]], 1);
        atomicAdd(&g_cntout[src[t]], 1);
    }
}

// ---------------- single-block prefix scan (both arrays) --------------------
__global__ __launch_bounds__(1024) void k_scan(int n) {
    __shared__ int pa[1024];
    __shared__ int pb[1024];
    int tid = threadIdx.x;
    int C = (n + 1023) / 1024;
    int s0 = tid * C, s1 = min(n, s0 + C);

    int suma = 0, sumb = 0;
    for (int i = s0; i < s1; i++) { suma += g_cntin[i]; sumb += g_cntout[i]; }
    pa[tid] = suma; pb[tid] = sumb;
    __syncthreads();

    // Kogge-Stone inclusive scan
    for (int off = 1; off < 1024; off <<= 1) {
        int a = (tid >= off) ? pa[tid - off] : 0;
        int b = (tid >= off) ? pb[tid - off] : 0;
        __syncthreads();
        pa[tid] += a; pb[tid] += b;
        __syncthreads();
    }

    int runa = pa[tid] - suma;   // exclusive prefix at chunk start
    int runb = pb[tid] - sumb;
    for (int i = s0; i < s1; i++) {
        g_offin [i] = runa; g_curin [i] = runa; runa += g_cntin [i];
        g_offout[i] = runb; g_curout[i] = runb; runb += g_cntout[i];
    }
    if (tid == 1023) { g_offin[n] = pa[1023]; g_offout[n] = pb[1023]; }
}

// ---------------- CSR placement ----------------------------------------------
__global__ void k_place(const int* __restrict__ src, const int* __restrict__ dst, int e) {
    int t = blockIdx.x * blockDim.x + threadIdx.x;
    if (t < e) {
        int s = src[t], d = dst[t];
        int p1 = atomicAdd(&g_curin [d], 1); g_csrin [p1] = s;
        int p2 = atomicAdd(&g_curout[s], 1); g_csrout[p2] = d;
    }
}

// ---------------- dinv --------------------------------------------------------
__global__ void k_dinv(int n) {
    int t = blockIdx.x * blockDim.x + threadIdx.x;
    if (t < n) {
        g_dinv_in [t] = rsqrtf(1.0f + (float)g_cntin [t]);   // +1 self-loop
        g_dinv_out[t] = rsqrtf(1.0f + (float)g_cntout[t]);
    }
}

// ---------------- fused dual GEMM + dinv pre-scale ---------------------------
// 256 threads, 64 rows per block, 4 rows per thread (weight-LDS amortized 4x).
__global__ __launch_bounds__(256) void k_gemm(const float* __restrict__ xin,
                                              const float* __restrict__ Win,
                                              const float* __restrict__ Wout,
                                              int n) {
    __shared__ float xs[64 * 64];
    __shared__ float wi[64 * 64];
    __shared__ float wo[64 * 64];
    const float* x = xin ? xin : g_h;

    int tid = threadIdx.x;
    {
        float4* wi4 = (float4*)wi; const float4* Wi4 = (const float4*)Win;
        float4* wo4 = (float4*)wo; const float4* Wo4 = (const float4*)Wout;
        #pragma unroll
        for (int i = tid; i < 1024; i += 256) { wi4[i] = Wi4[i]; wo4[i] = Wo4[i]; }
    }
    int base = blockIdx.x * 64;
    {
        const float4* x4 = (const float4*)x;
        #pragma unroll
        for (int i = tid; i < 1024; i += 256) {
            int r = i >> 4;
            int row = base + r;
            ((float4*)xs)[i] = (row < n) ? x4[row * 16 + (i & 15)]
                                         : make_float4(0.f, 0.f, 0.f, 0.f);
        }
    }
    __syncthreads();

    int fq = tid & 15;                // float4 column group
    int rg = tid >> 4;                // row group 0..15 (4 rows each)
    int r0 = rg * 4;

    float4 ai[4], ao[4];
    #pragma unroll
    for (int r = 0; r < 4; r++) {
        ai[r] = make_float4(0.f, 0.f, 0.f, 0.f);
        ao[r] = make_float4(0.f, 0.f, 0.f, 0.f);
    }
    const float4* wi4 = (const float4*)wi;
    const float4* wo4 = (const float4*)wo;
    #pragma unroll
    for (int k = 0; k < 64; k++) {
        float4 a = wi4[k * 16 + fq];
        float4 b = wo4[k * 16 + fq];
        #pragma unroll
        for (int r = 0; r < 4; r++) {
            float xk = xs[(r0 + r) * 64 + k];
            ai[r].x += xk * a.x; ai[r].y += xk * a.y; ai[r].z += xk * a.z; ai[r].w += xk * a.w;
            ao[r].x += xk * b.x; ao[r].y += xk * b.y; ao[r].z += xk * b.z; ao[r].w += xk * b.w;
        }
    }
    #pragma unroll
    for (int r = 0; r < 4; r++) {
        int row = base + r0 + r;
        if (row >= n) break;
        float di = g_dinv_in[row], dq = g_dinv_out[row];
        float4 pi = make_float4(ai[r].x * di, ai[r].y * di, ai[r].z * di, ai[r].w * di);
        float4 po = make_float4(ao[r].x * dq, ao[r].y * dq, ao[r].z * dq, ao[r].w * dq);
        ((float4*)g_pin )[row * 16 + fq] = pi;
        ((float4*)g_pout)[row * 16 + fq] = po;
    }
}

// ---------------- gather + combine + relu (replaces scatter+combine) --------
// 16 threads per node; self-loop is the accumulator seed.
__global__ __launch_bounds__(256) void k_gather(const float* __restrict__ bin,
                                                const float* __restrict__ bout,
                                                int n, int doRelu) {
    int t = blockIdx.x * blockDim.x + threadIdx.x;
    int v = t >> 4;
    if (v >= n) return;
    int fq = t & 15;
    const float4* pin4  = (const float4*)g_pin;
    const float4* pout4 = (const float4*)g_pout;

    // in-direction: sum p_in over in-neighbors (+ self)
    float4 ai = pin4[v * 16 + fq];
    {
        int i = g_offin[v], e1 = g_offin[v + 1];
        if (i < e1) {
            int s = g_csrin[i];
            for (; i + 1 < e1; i++) {
                int snext = g_csrin[i + 1];           // prefetch next index
                float4 m = pin4[s * 16 + fq];
                ai.x += m.x; ai.y += m.y; ai.z += m.z; ai.w += m.w;
                s = snext;
            }
            float4 m = pin4[s * 16 + fq];
            ai.x += m.x; ai.y += m.y; ai.z += m.z; ai.w += m.w;
        }
    }
    // out-direction: sum p_out over out-neighbors (+ self)
    float4 ao = pout4[v * 16 + fq];
    {
        int i = g_offout[v], e1 = g_offout[v + 1];
        if (i < e1) {
            int d = g_csrout[i];
            for (; i + 1 < e1; i++) {
                int dnext = g_csrout[i + 1];
                float4 m = pout4[d * 16 + fq];
                ao.x += m.x; ao.y += m.y; ao.z += m.z; ao.w += m.w;
                d = dnext;
            }
            float4 m = pout4[d * 16 + fq];
            ao.x += m.x; ao.y += m.y; ao.z += m.z; ao.w += m.w;
        }
    }

    float di = g_dinv_in[v], dq = g_dinv_out[v];
    float4 bi = ((const float4*)bin)[fq];
    float4 bo = ((const float4*)bout)[fq];
    float4 r;
    r.x = 0.5f * (ao.x * dq + bo.x) + 0.5f * (ai.x * di + bi.x);
    r.y = 0.5f * (ao.y * dq + bo.y) + 0.5f * (ai.y * di + bi.y);
    r.z = 0.5f * (ao.z * dq + bo.z) + 0.5f * (ai.z * di + bi.z);
    r.w = 0.5f * (ao.w * dq + bo.w) + 0.5f * (ai.w * di + bi.w);
    if (doRelu) {
        r.x = fmaxf(r.x, 0.f); r.y = fmaxf(r.y, 0.f);
        r.z = fmaxf(r.z, 0.f); r.w = fmaxf(r.w, 0.f);
    }
    ((float4*)g_h)[v * 16 + fq] = r;
}

// ---------------- pooling -----------------------------------------------------
__global__ void k_pool(const int* __restrict__ batch, int n) {
    __shared__ float sm[NG * F];
    __shared__ float smc[NG];
    int tid = threadIdx.x;                 // 256
    for (int i = tid; i < NG * F; i += 256) sm[i] = 0.f;
    if (tid < NG) smc[tid] = 0.f;
    __syncthreads();

    int per = (n + gridDim.x - 1) / gridDim.x;
    int b0 = blockIdx.x * per;
    int b1 = min(n, b0 + per);
    for (int i = b0 * 64 + tid; i < b1 * 64; i += 256) {
        int node = i >> 6, f = i & 63;
        atomicAdd(&sm[batch[node] * 64 + f], g_h[i]);
    }
    for (int node = b0 + tid; node < b1; node += 256)
        atomicAdd(&smc[batch[node]], 1.0f);
    __syncthreads();

    for (int i = tid; i < NG * F; i += 256)
        if (sm[i] != 0.f) atomicAdd(&g_pool[i], sm[i]);
    if (tid < NG && smc[tid] != 0.f) atomicAdd(&g_cnt[tid], smc[tid]);
}

// ---------------- head: mean, LayerNorm, MLP ---------------------------------
__global__ void k_head(const float* __restrict__ lnw, const float* __restrict__ lnb,
                       const float* __restrict__ P1w, const float* __restrict__ P1b,
                       const float* __restrict__ P2w, const float* __restrict__ P2b,
                       float* __restrict__ out) {
    __shared__ float z [NG * F];
    __shared__ float h1[NG * 128];
    int tid = threadIdx.x;           // 128

    if (tid < NG) {
        int g = tid;
        float c = fmaxf(g_cnt[g], 1.0f);
        float inv = 1.0f / c;
        float mu = 0.f;
        for (int f = 0; f < 64; f++) mu += g_pool[g * 64 + f];
        mu *= inv * (1.0f / 64.0f);
        float var = 0.f;
        for (int f = 0; f < 64; f++) {
            float d = g_pool[g * 64 + f] * inv - mu;
            var += d * d;
        }
        var *= (1.0f / 64.0f);
        float rs = rsqrtf(var + 1e-5f);
        for (int f = 0; f < 64; f++)
            z[g * 64 + f] = (g_pool[g * 64 + f] * inv - mu) * rs * lnw[f] + lnb[f];
    }
    __syncthreads();

    for (int idx = tid; idx < NG * 128; idx += 128) {
        int g = idx >> 7, j = idx & 127;
        float s = P1b[j];
        for (int k = 0; k < 64; k++) s += z[g * 64 + k] * P1w[k * 128 + j];
        h1[idx] = fmaxf(s, 0.f);
    }
    __syncthreads();

    {
        int g = tid >> 1, o = tid & 1;
        float s = P2b[o];
        for (int j = 0; j < 128; j++) s += h1[g * 128 + j] * P2w[j * 2 + o];
        out[g * 2 + o] = s;
    }
}

// ---------------- launch -----------------------------------------------------
extern "C" void kernel_launch(void* const* d_in, const int* in_sizes, int n_in,
                              void* d_out, int out_size) {
    const float* x     = (const float*)d_in[0];
    const int*   src   = (const int*)  d_in[1];
    const int*   dst   = (const int*)  d_in[2];
    const int*   batch = (const int*)  d_in[3];
    const float* W1_in = (const float*)d_in[4];
    const float* b1_in = (const float*)d_in[5];
    const float* W1_out= (const float*)d_in[6];
    const float* b1_out= (const float*)d_in[7];
    const float* W2_in = (const float*)d_in[8];
    const float* b2_in = (const float*)d_in[9];
    const float* W2_out= (const float*)d_in[10];
    const float* b2_out= (const float*)d_in[11];
    const float* W3_in = (const float*)d_in[12];
    const float* b3_in = (const float*)d_in[13];
    const float* W3_out= (const float*)d_in[14];
    const float* b3_out= (const float*)d_in[15];
    const float* ln_w  = (const float*)d_in[16];
    const float* ln_b  = (const float*)d_in[17];
    const float* P1_w  = (const float*)d_in[18];
    const float* P1_b  = (const float*)d_in[19];
    const float* P2_w  = (const float*)d_in[20];
    const float* P2_b  = (const float*)d_in[21];
    float* out = (float*)d_out;

    int n = in_sizes[0] / 64;   // 50000
    int e = in_sizes[1];        // 800000

    int ib = (n + 255) / 256;
    k_init <<<ib, 256>>>(n);
    k_count<<<(e + 255) / 256, 256>>>(src, dst, e);
    k_scan <<<1, 1024>>>(n);
    k_place<<<(e + 255) / 256, 256>>>(src, dst, e);
    k_dinv <<<ib, 256>>>(n);

    int gemmBlocks = (n + 63) / 64;
    int gathBlocks = (n * 16 + 255) / 256;

    // layer 1
    k_gemm  <<<gemmBlocks, 256>>>(x, W1_in, W1_out, n);
    k_gather<<<gathBlocks, 256>>>(b1_in, b1_out, n, 1);
    // layer 2
    k_gemm  <<<gemmBlocks, 256>>>(nullptr, W2_in, W2_out, n);
    k_gather<<<gathBlocks, 256>>>(b2_in, b2_out, n, 1);
    // layer 3
    k_gemm  <<<gemmBlocks, 256>>>(nullptr, W3_in, W3_out, n);
    k_gather<<<gathBlocks, 256>>>(b3_in, b3_out, n, 0);

    k_pool<<<128, 256>>>(batch, n);
    k_head<<<1, 128>>>(ln_w, ln_b, P1_w, P1_b, P2_w, P2_b, out);
}

// round 3
// speedup vs baseline: 2.8312x; 1.3939x over previous
#include <cuda_runtime.h>

#define NN 50000
#define EE 800000
#define F  64
#define NG 64

// ---------------- scratch (device globals) ----------------------------------
__device__ float g_dinv_in [NN];
__device__ float g_dinv_out[NN];
__device__ float g_pin   [NN * F];
__device__ float g_pout  [NN * F];
__device__ float g_h     [NN * F];
__device__ float g_pool  [NG * F];
__device__ float g_cnt   [NG];

__device__ int g_cntin [NN];
__device__ int g_cntout[NN];
__device__ int g_offin [NN + 1];
__device__ int g_offout[NN + 1];
__device__ int g_curin [NN];
__device__ int g_curout[NN];
__device__ int g_csrin [EE];
__device__ int g_csrout[EE];
__device__ int g_cbin  [1024];
__device__ int g_cbout [1024];

// ---------------- init -------------------------------------------------------
__global__ void k_init(int n) {
    int t = blockIdx.x * blockDim.x + threadIdx.x;
    if (t < n) { g_cntin[t] = 0; g_cntout[t] = 0; }
    if (t < NG * F) g_pool[t] = 0.0f;
    if (t < NG) g_cnt[t] = 0.0f;
}

// ---------------- degree histogram: 4 edges per thread (REDG, MLP=8) -------
__global__ void k_count(const int* __restrict__ src, const int* __restrict__ dst, int e) {
    int t = blockIdx.x * blockDim.x + threadIdx.x;
    int i = t * 4;
    if (i + 3 < e) {
        int4 s4 = ((const int4*)src)[t];
        int4 d4 = ((const int4*)dst)[t];
        atomicAdd(&g_cntin[d4.x], 1); atomicAdd(&g_cntout[s4.x], 1);
        atomicAdd(&g_cntin[d4.y], 1); atomicAdd(&g_cntout[s4.y], 1);
        atomicAdd(&g_cntin[d4.z], 1); atomicAdd(&g_cntout[s4.z], 1);
        atomicAdd(&g_cntin[d4.w], 1); atomicAdd(&g_cntout[s4.w], 1);
    } else {
        for (; i < e; i++) {
            atomicAdd(&g_cntin[dst[i]], 1);
            atomicAdd(&g_cntout[src[i]], 1);
        }
    }
}

// ---------------- scan part A: chunk sums + block scan ----------------------
__global__ __launch_bounds__(1024) void k_scanA(int n) {
    __shared__ int pa[1024];
    __shared__ int pb[1024];
    int tid = threadIdx.x;
    int C = (n + 1023) / 1024;
    int s0 = tid * C, s1 = min(n, s0 + C);

    int suma = 0, sumb = 0;
    for (int i = s0; i < s1; i++) { suma += g_cntin[i]; sumb += g_cntout[i]; }
    pa[tid] = suma; pb[tid] = sumb;
    __syncthreads();

    for (int off = 1; off < 1024; off <<= 1) {
        int a = (tid >= off) ? pa[tid - off] : 0;
        int b = (tid >= off) ? pb[tid - off] : 0;
        __syncthreads();
        pa[tid] += a; pb[tid] += b;
        __syncthreads();
    }
    g_cbin [tid] = pa[tid] - suma;   // exclusive chunk base
    g_cbout[tid] = pb[tid] - sumb;
    if (tid == 1023) { g_offin[n] = pa[1023]; g_offout[n] = pb[1023]; }
}

// ---------------- scan part B: distributed writeback + dinv ----------------
__global__ void k_scanB(int n) {
    int tid = blockIdx.x * blockDim.x + threadIdx.x;   // 0..1023, 32 blocks x 32
    int C = (n + 1023) / 1024;
    int s0 = tid * C, s1 = min(n, s0 + C);
    int runa = g_cbin[tid], runb = g_cbout[tid];
    for (int i = s0; i < s1; i++) {
        int ca = g_cntin[i], cb = g_cntout[i];
        g_offin [i] = runa; g_curin [i] = runa; runa += ca;
        g_offout[i] = runb; g_curout[i] = runb; runb += cb;
        g_dinv_in [i] = rsqrtf(1.0f + (float)ca);
        g_dinv_out[i] = rsqrtf(1.0f + (float)cb);
    }
}

// ---------------- CSR placement: 4 edges per thread -------------------------
__global__ void k_place(const int* __restrict__ src, const int* __restrict__ dst, int e) {
    int t = blockIdx.x * blockDim.x + threadIdx.x;
    int i = t * 4;
    if (i + 3 < e) {
        int4 s4 = ((const int4*)src)[t];
        int4 d4 = ((const int4*)dst)[t];
        int p0 = atomicAdd(&g_curin [d4.x], 1);
        int p1 = atomicAdd(&g_curin [d4.y], 1);
        int p2 = atomicAdd(&g_curin [d4.z], 1);
        int p3 = atomicAdd(&g_curin [d4.w], 1);
        g_csrin[p0] = s4.x; g_csrin[p1] = s4.y; g_csrin[p2] = s4.z; g_csrin[p3] = s4.w;
        int q0 = atomicAdd(&g_curout[s4.x], 1);
        int q1 = atomicAdd(&g_curout[s4.y], 1);
        int q2 = atomicAdd(&g_curout[s4.z], 1);
        int q3 = atomicAdd(&g_curout[s4.w], 1);
        g_csrout[q0] = d4.x; g_csrout[q1] = d4.y; g_csrout[q2] = d4.z; g_csrout[q3] = d4.w;
    } else {
        for (; i < e; i++) {
            int s = src[i], d = dst[i];
            int p = atomicAdd(&g_curin [d], 1); g_csrin [p] = s;
            int q = atomicAdd(&g_curout[s], 1); g_csrout[q] = d;
        }
    }
}

// ---------------- fused dual GEMM + dinv pre-scale ---------------------------
__global__ __launch_bounds__(256) void k_gemm(const float* __restrict__ xin,
                                              const float* __restrict__ Win,
                                              const float* __restrict__ Wout,
                                              int n) {
    __shared__ float xs[64 * 64];
    __shared__ float wi[64 * 64];
    __shared__ float wo[64 * 64];
    const float* x = xin ? xin : g_h;

    int tid = threadIdx.x;
    {
        float4* wi4 = (float4*)wi; const float4* Wi4 = (const float4*)Win;
        float4* wo4 = (float4*)wo; const float4* Wo4 = (const float4*)Wout;
        #pragma unroll
        for (int i = tid; i < 1024; i += 256) { wi4[i] = Wi4[i]; wo4[i] = Wo4[i]; }
    }
    int base = blockIdx.x * 64;
    {
        const float4* x4 = (const float4*)x;
        #pragma unroll
        for (int i = tid; i < 1024; i += 256) {
            int r = i >> 4;
            int row = base + r;
            ((float4*)xs)[i] = (row < n) ? x4[row * 16 + (i & 15)]
                                         : make_float4(0.f, 0.f, 0.f, 0.f);
        }
    }
    __syncthreads();

    int fq = tid & 15;
    int rg = tid >> 4;
    int r0 = rg * 4;

    float4 ai[4], ao[4];
    #pragma unroll
    for (int r = 0; r < 4; r++) {
        ai[r] = make_float4(0.f, 0.f, 0.f, 0.f);
        ao[r] = make_float4(0.f, 0.f, 0.f, 0.f);
    }
    const float4* wi4 = (const float4*)wi;
    const float4* wo4 = (const float4*)wo;
    #pragma unroll
    for (int k = 0; k < 64; k++) {
        float4 a = wi4[k * 16 + fq];
        float4 b = wo4[k * 16 + fq];
        #pragma unroll
        for (int r = 0; r < 4; r++) {
            float xk = xs[(r0 + r) * 64 + k];
            ai[r].x += xk * a.x; ai[r].y += xk * a.y; ai[r].z += xk * a.z; ai[r].w += xk * a.w;
            ao[r].x += xk * b.x; ao[r].y += xk * b.y; ao[r].z += xk * b.z; ao[r].w += xk * b.w;
        }
    }
    #pragma unroll
    for (int r = 0; r < 4; r++) {
        int row = base + r0 + r;
        if (row >= n) break;
        float di = g_dinv_in[row], dq = g_dinv_out[row];
        float4 pi = make_float4(ai[r].x * di, ai[r].y * di, ai[r].z * di, ai[r].w * di);
        float4 po = make_float4(ao[r].x * dq, ao[r].y * dq, ao[r].z * dq, ao[r].w * dq);
        ((float4*)g_pin )[row * 16 + fq] = pi;
        ((float4*)g_pout)[row * 16 + fq] = po;
    }
}

// ---------------- gather: one WARP per node, shfl-distributed indices --------
__global__ __launch_bounds__(256) void k_gather(const float* __restrict__ bin,
                                                const float* __restrict__ bout,
                                                int n, int doRelu) {
    int v = (blockIdx.x * 256 + threadIdx.x) >> 5;
    if (v >= n) return;
    int lane = threadIdx.x & 31;
    int fq   = lane & 15;
    int half = lane >> 4;
    const float4* pin4  = (const float4*)g_pin;
    const float4* pout4 = (const float4*)g_pout;

    // ---- in direction: sum p_in over in-neighbors + self
    float4 a1 = make_float4(0.f, 0.f, 0.f, 0.f);
    float4 a2 = make_float4(0.f, 0.f, 0.f, 0.f);
    if (half == 0) a1 = pin4[v * 16 + fq];           // self-loop seed
    {
        int i0 = g_offin[v], i1 = g_offin[v + 1];
        for (int base = i0; base < i1; base += 32) {
            int cnt = min(32, i1 - base);
            int idx = 0;
            if (lane < cnt) idx = g_csrin[base + lane];
            for (int j = 0; j < cnt; j += 4) {
                int j1 = j + half, j2 = j + 2 + half;
                int s1 = __shfl_sync(0xffffffffu, idx, j1 & 31);
                int s2 = __shfl_sync(0xffffffffu, idx, j2 & 31);
                if (j1 < cnt) {
                    float4 m = pin4[s1 * 16 + fq];
                    a1.x += m.x; a1.y += m.y; a1.z += m.z; a1.w += m.w;
                }
                if (j2 < cnt) {
                    float4 m = pin4[s2 * 16 + fq];
                    a2.x += m.x; a2.y += m.y; a2.z += m.z; a2.w += m.w;
                }
            }
        }
    }
    float4 ain = make_float4(a1.x + a2.x, a1.y + a2.y, a1.z + a2.z, a1.w + a2.w);

    // ---- out direction: sum p_out over out-neighbors + self
    float4 b1 = make_float4(0.f, 0.f, 0.f, 0.f);
    float4 b2 = make_float4(0.f, 0.f, 0.f, 0.f);
    if (half == 0) b1 = pout4[v * 16 + fq];
    {
        int i0 = g_offout[v], i1 = g_offout[v + 1];
        for (int base = i0; base < i1; base += 32) {
            int cnt = min(32, i1 - base);
            int idx = 0;
            if (lane < cnt) idx = g_csrout[base + lane];
            for (int j = 0; j < cnt; j += 4) {
                int j1 = j + half, j2 = j + 2 + half;
                int s1 = __shfl_sync(0xffffffffu, idx, j1 & 31);
                int s2 = __shfl_sync(0xffffffffu, idx, j2 & 31);
                if (j1 < cnt) {
                    float4 m = pout4[s1 * 16 + fq];
                    b1.x += m.x; b1.y += m.y; b1.z += m.z; b1.w += m.w;
                }
                if (j2 < cnt) {
                    float4 m = pout4[s2 * 16 + fq];
                    b2.x += m.x; b2.y += m.y; b2.z += m.z; b2.w += m.w;
                }
            }
        }
    }
    float4 aout = make_float4(b1.x + b2.x, b1.y + b2.y, b1.z + b2.z, b1.w + b2.w);

    // ---- reduce across halves (lanes 0-15 get totals)
    ain.x  += __shfl_xor_sync(0xffffffffu, ain.x,  16);
    ain.y  += __shfl_xor_sync(0xffffffffu, ain.y,  16);
    ain.z  += __shfl_xor_sync(0xffffffffu, ain.z,  16);
    ain.w  += __shfl_xor_sync(0xffffffffu, ain.w,  16);
    aout.x += __shfl_xor_sync(0xffffffffu, aout.x, 16);
    aout.y += __shfl_xor_sync(0xffffffffu, aout.y, 16);
    aout.z += __shfl_xor_sync(0xffffffffu, aout.z, 16);
    aout.w += __shfl_xor_sync(0xffffffffu, aout.w, 16);

    if (half == 0) {
        float di = g_dinv_in[v], dq = g_dinv_out[v];
        float4 bi = ((const float4*)bin)[fq];
        float4 bo = ((const float4*)bout)[fq];
        float4 r;
        r.x = 0.5f * (aout.x * dq + bo.x) + 0.5f * (ain.x * di + bi.x);
        r.y = 0.5f * (aout.y * dq + bo.y) + 0.5f * (ain.y * di + bi.y);
        r.z = 0.5f * (aout.z * dq + bo.z) + 0.5f * (ain.z * di + bi.z);
        r.w = 0.5f * (aout.w * dq + bo.w) + 0.5f * (ain.w * di + bi.w);
        if (doRelu) {
            r.x = fmaxf(r.x, 0.f); r.y = fmaxf(r.y, 0.f);
            r.z = fmaxf(r.z, 0.f); r.w = fmaxf(r.w, 0.f);
        }
        ((float4*)g_h)[v * 16 + fq] = r;
    }
}

// ---------------- pooling -----------------------------------------------------
__global__ void k_pool(const int* __restrict__ batch, int n) {
    __shared__ float sm[NG * F];
    __shared__ float smc[NG];
    int tid = threadIdx.x;                 // 256
    for (int i = tid; i < NG * F; i += 256) sm[i] = 0.f;
    if (tid < NG) smc[tid] = 0.f;
    __syncthreads();

    int per = (n + gridDim.x - 1) / gridDim.x;
    int b0 = blockIdx.x * per;
    int b1 = min(n, b0 + per);
    for (int i = b0 * 64 + tid; i < b1 * 64; i += 256) {
        int node = i >> 6, f = i & 63;
        atomicAdd(&sm[batch[node] * 64 + f], g_h[i]);
    }
    for (int node = b0 + tid; node < b1; node += 256)
        atomicAdd(&smc[batch[node]], 1.0f);
    __syncthreads();

    for (int i = tid; i < NG * F; i += 256)
        if (sm[i] != 0.f) atomicAdd(&g_pool[i], sm[i]);
    if (tid < NG && smc[tid] != 0.f) atomicAdd(&g_cnt[tid], smc[tid]);
}

// ---------------- head: mean, LayerNorm, MLP ---------------------------------
__global__ void k_head(const float* __restrict__ lnw, const float* __restrict__ lnb,
                       const float* __restrict__ P1w, const float* __restrict__ P1b,
                       const float* __restrict__ P2w, const float* __restrict__ P2b,
                       float* __restrict__ out) {
    __shared__ float z [NG * F];
    __shared__ float h1[NG * 128];
    int tid = threadIdx.x;           // 128

    if (tid < NG) {
        int g = tid;
        float c = fmaxf(g_cnt[g], 1.0f);
        float inv = 1.0f / c;
        float mu = 0.f;
        for (int f = 0; f < 64; f++) mu += g_pool[g * 64 + f];
        mu *= inv * (1.0f / 64.0f);
        float var = 0.f;
        for (int f = 0; f < 64; f++) {
            float d = g_pool[g * 64 + f] * inv - mu;
            var += d * d;
        }
        var *= (1.0f / 64.0f);
        float rs = rsqrtf(var + 1e-5f);
        for (int f = 0; f < 64; f++)
            z[g * 64 + f] = (g_pool[g * 64 + f] * inv - mu) * rs * lnw[f] + lnb[f];
    }
    __syncthreads();

    for (int idx = tid; idx < NG * 128; idx += 128) {
        int g = idx >> 7, j = idx & 127;
        float s = P1b[j];
        for (int k = 0; k < 64; k++) s += z[g * 64 + k] * P1w[k * 128 + j];
        h1[idx] = fmaxf(s, 0.f);
    }
    __syncthreads();

    {
        int g = tid >> 1, o = tid & 1;
        float s = P2b[o];
        for (int j = 0; j < 128; j++) s += h1[g * 128 + j] * P2w[j * 2 + o];
        out[g * 2 + o] = s;
    }
}

// ---------------- launch -----------------------------------------------------
extern "C" void kernel_launch(void* const* d_in, const int* in_sizes, int n_in,
                              void* d_out, int out_size) {
    const float* x     = (const float*)d_in[0];
    const int*   src   = (const int*)  d_in[1];
    const int*   dst   = (const int*)  d_in[2];
    const int*   batch = (const int*)  d_in[3];
    const float* W1_in = (const float*)d_in[4];
    const float* b1_in = (const float*)d_in[5];
    const float* W1_out= (const float*)d_in[6];
    const float* b1_out= (const float*)d_in[7];
    const float* W2_in = (const float*)d_in[8];
    const float* b2_in = (const float*)d_in[9];
    const float* W2_out= (const float*)d_in[10];
    const float* b2_out= (const float*)d_in[11];
    const float* W3_in = (const float*)d_in[12];
    const float* b3_in = (const float*)d_in[13];
    const float* W3_out= (const float*)d_in[14];
    const float* b3_out= (const float*)d_in[15];
    const float* ln_w  = (const float*)d_in[16];
    const float* ln_b  = (const float*)d_in[17];
    const float* P1_w  = (const float*)d_in[18];
    const float* P1_b  = (const float*)d_in[19];
    const float* P2_w  = (const float*)d_in[20];
    const float* P2_b  = (const float*)d_in[21];
    float* out = (float*)d_out;

    int n = in_sizes[0] / 64;   // 50000
    int e = in_sizes[1];        // 800000

    int ib = (n + 255) / 256;
    int eb4 = ((e + 3) / 4 + 255) / 256;
    k_init <<<ib, 256>>>(n);
    k_count<<<eb4, 256>>>(src, dst, e);
    k_scanA<<<1, 1024>>>(n);
    k_scanB<<<32, 32>>>(n);
    k_place<<<eb4, 256>>>(src, dst, e);

    int gemmBlocks = (n + 63) / 64;
    int gathBlocks = (n * 32 + 255) / 256;

    // layer 1
    k_gemm  <<<gemmBlocks, 256>>>(x, W1_in, W1_out, n);
    k_gather<<<gathBlocks, 256>>>(b1_in, b1_out, n, 1);
    // layer 2
    k_gemm  <<<gemmBlocks, 256>>>(nullptr, W2_in, W2_out, n);
    k_gather<<<gathBlocks, 256>>>(b2_in, b2_out, n, 1);
    // layer 3
    k_gemm  <<<gemmBlocks, 256>>>(nullptr, W3_in, W3_out, n);
    k_gather<<<gathBlocks, 256>>>(b3_in, b3_out, n, 0);

    k_pool<<<128, 256>>>(batch, n);
    k_head<<<1, 128>>>(ln_w, ln_b, P1_w, P1_b, P2_w, P2_b, out);
}